// round 8
// baseline (speedup 1.0000x reference)
#include <cuda_runtime.h>
#include <cstdint>

#define FF 128
#define HH 512
#define MAXN 50048
#define MAXE 401408
#define SCAN_B 1024

// Scratch (static device globals — no runtime allocation allowed)
__device__ float g_h[(size_t)50000 * HH];   // h' = (x @ W^T) * dinv[row]
__device__ int   g_cnt[MAXN];               // zero-initialized at load; re-zeroed by scan
__device__ float g_dinv[MAXN];
__device__ int   g_rowptr[MAXN + 1];
__device__ int   g_cur[MAXN];
__device__ int   g_srcidx[MAXE];
__device__ int   g_bsum[256];
__device__ int   g_boff[256];

// ---------------------------------------------------------------------------
// CSR build: count -> scan(+dinv, +re-zero) -> fill
// ---------------------------------------------------------------------------
__global__ void count_kernel(const int* __restrict__ ei, int E, int n) {
    int e = blockIdx.x * blockDim.x + threadIdx.x;
    if (e < E) {
        int c = ei[E + e];
        if ((unsigned)c < (unsigned)n) atomicAdd(&g_cnt[c], 1);
    }
}

// Per-block scan; also computes dinv and re-zeroes g_cnt for the next replay.
__global__ void scan_block_kernel(int n) {
    __shared__ int sh[SCAN_B];
    int gid = blockIdx.x * SCAN_B + threadIdx.x;
    int v = 0;
    if (gid < n) {
        v = g_cnt[gid];
        g_cnt[gid] = 0;                           // restore zeros for determinism
        g_dinv[gid] = rsqrtf((float)(v + 1));     // +1 self-loop
    }
    sh[threadIdx.x] = v;
    __syncthreads();
#pragma unroll
    for (int off = 1; off < SCAN_B; off <<= 1) {
        int t = (threadIdx.x >= off) ? sh[threadIdx.x - off] : 0;
        __syncthreads();
        sh[threadIdx.x] += t;
        __syncthreads();
    }
    if (gid < n) g_rowptr[gid] = sh[threadIdx.x] - v;   // exclusive
    if (threadIdx.x == SCAN_B - 1) g_bsum[blockIdx.x] = sh[threadIdx.x];
}

__global__ void scan_sums_kernel(int nb) {
    __shared__ int sh[256];
    int v = (threadIdx.x < nb) ? g_bsum[threadIdx.x] : 0;
    sh[threadIdx.x] = v;
    __syncthreads();
#pragma unroll
    for (int off = 1; off < 256; off <<= 1) {
        int t = (threadIdx.x >= off) ? sh[threadIdx.x - off] : 0;
        __syncthreads();
        sh[threadIdx.x] += t;
        __syncthreads();
    }
    if (threadIdx.x < nb) g_boff[threadIdx.x] = sh[threadIdx.x] - v;  // exclusive
}

__global__ void add_off_kernel(int n, int E) {
    int i = blockIdx.x * blockDim.x + threadIdx.x;
    if (i < n) {
        int v = g_rowptr[i] + g_boff[i / SCAN_B];
        g_rowptr[i] = v;
        g_cur[i] = v;
    }
    if (i == 0) g_rowptr[n] = E;
}

__global__ void fill_kernel(const int* __restrict__ ei, int E, int n) {
    int e = blockIdx.x * blockDim.x + threadIdx.x;
    if (e < E) {
        int r = ei[e];
        int c = ei[E + e];
        if ((unsigned)r < (unsigned)n && (unsigned)c < (unsigned)n) {
            int pos = atomicAdd(&g_cur[c], 1);
            g_srcidx[pos] = r;
        }
    }
}

// ---------------------------------------------------------------------------
// tf32 tensor-core GEMM, classic 2D tiling, double-buffered cp.async A and B.
// BM=128, BN=128, BK=32, 256 threads (8 warps, warp tile 32x64).
// ---------------------------------------------------------------------------
#define TLD 36
#define TILE_BYTES (128 * TLD * 4)                  // 18432 per buffer per operand
#define SMEM_TOTAL_GEMM (4 * TILE_BYTES)            // 73728

__device__ __forceinline__ uint32_t f2tf(float x) {
    uint32_t u;
    asm("cvt.rna.tf32.f32 %0, %1;" : "=r"(u) : "f"(x));
    return u;
}

__device__ __forceinline__ void mma8(float* c, const uint32_t* a,
                                     uint32_t b0, uint32_t b1) {
    asm volatile(
        "mma.sync.aligned.m16n8k8.row.col.f32.tf32.tf32.f32 "
        "{%0,%1,%2,%3}, {%4,%5,%6,%7}, {%8,%9}, {%0,%1,%2,%3};"
        : "+f"(c[0]), "+f"(c[1]), "+f"(c[2]), "+f"(c[3])
        : "r"(a[0]), "r"(a[1]), "r"(a[2]), "r"(a[3]), "r"(b0), "r"(b1));
}

__device__ __forceinline__ void cp_async16(void* sptr, const void* gptr) {
    uint32_t sa = (uint32_t)__cvta_generic_to_shared(sptr);
    asm volatile("cp.async.cg.shared.global [%0], [%1], 16;" :: "r"(sa), "l"(gptr));
}
__device__ __forceinline__ void cp_commit() {
    asm volatile("cp.async.commit_group;");
}
template <int NN>
__device__ __forceinline__ void cp_wait() {
    asm volatile("cp.async.wait_group %0;" :: "n"(NN));
}

__global__ __launch_bounds__(256, 2) void tf32_gemm_kernel(
        const float* __restrict__ X, const float* __restrict__ W, int M) {
    extern __shared__ char smem_raw[];
    float (*As)[128][TLD] = (float(*)[128][TLD])smem_raw;
    float (*Bs)[128][TLD] = (float(*)[128][TLD])(smem_raw + 2 * TILE_BYTES);

    const int t    = threadIdx.x;
    const int wid  = t >> 5;
    const int lane = t & 31;
    const int warp_m = wid & 3;   // 4 warps along M (32 rows each)
    const int warp_n = wid >> 2;  // 2 warps along N (64 cols each)
    const int bn = blockIdx.x * 128;
    const int bm = blockIdx.y * 128;
    const int fr = lane >> 2;     // 0..7
    const int fc = lane & 3;      // 0..3

    // per-thread load coords: 4 float4 per operand per k-step
    const int lrow = t >> 3;      // 0..31 (advance by 32 rows per i)
    const int lc4  = t & 7;       // 0..7

    auto issueAB = [&](int kt, int buf) {
#pragma unroll
        for (int i = 0; i < 4; i++) {
            int row = lrow + i * 32;
            int gm = bm + row; if (gm >= M) gm = M - 1;   // clamp; tail rows unused
            cp_async16(&As[buf][row][lc4 * 4],
                       &X[(size_t)gm * FF + kt * 32 + lc4 * 4]);
        }
#pragma unroll
        for (int i = 0; i < 4; i++) {
            int row = lrow + i * 32;
            cp_async16(&Bs[buf][row][lc4 * 4],
                       &W[(size_t)(bn + row) * FF + kt * 32 + lc4 * 4]);
        }
        cp_commit();
    };

    issueAB(0, 0);
    issueAB(1, 1);

    float c[2][8][4];
#pragma unroll
    for (int mt = 0; mt < 2; mt++)
#pragma unroll
        for (int j = 0; j < 8; j++)
#pragma unroll
            for (int q = 0; q < 4; q++) c[mt][j][q] = 0.f;

#pragma unroll
    for (int kt = 0; kt < 4; kt++) {
        const int buf = kt & 1;
        if (kt < 3) cp_wait<1>(); else cp_wait<0>();
        __syncthreads();

#pragma unroll
        for (int ks = 0; ks < 4; ks++) {
            const int kc = ks * 8 + fc;
            uint32_t a[2][4];
#pragma unroll
            for (int mt = 0; mt < 2; mt++) {
                int r = warp_m * 32 + mt * 16 + fr;
                a[mt][0] = f2tf(As[buf][r][kc]);
                a[mt][1] = f2tf(As[buf][r + 8][kc]);
                a[mt][2] = f2tf(As[buf][r][kc + 4]);
                a[mt][3] = f2tf(As[buf][r + 8][kc + 4]);
            }
#pragma unroll
            for (int j = 0; j < 8; j++) {
                int nr = warp_n * 64 + j * 8 + fr;
                uint32_t b0 = f2tf(Bs[buf][nr][kc]);
                uint32_t b1 = f2tf(Bs[buf][nr][kc + 4]);
#pragma unroll
                for (int mt = 0; mt < 2; mt++)
                    mma8(c[mt][j], a[mt], b0, b1);
            }
        }
        __syncthreads();
        if (kt + 2 <= 3) issueAB(kt + 2, buf);
    }

    // Epilogue: scale by dinv[row], float2 stores
#pragma unroll
    for (int mt = 0; mt < 2; mt++) {
        int r0 = bm + warp_m * 32 + mt * 16 + fr;
        int r1 = r0 + 8;
        float s0 = (r0 < M) ? g_dinv[r0] : 0.f;
        float s1 = (r1 < M) ? g_dinv[r1] : 0.f;
#pragma unroll
        for (int j = 0; j < 8; j++) {
            int col = bn + warp_n * 64 + j * 8 + fc * 2;
            if (r0 < M) {
                float2 v = make_float2(c[mt][j][0] * s0, c[mt][j][1] * s0);
                *(float2*)&g_h[(size_t)r0 * HH + col] = v;
            }
            if (r1 < M) {
                float2 v = make_float2(c[mt][j][2] * s1, c[mt][j][3] * s1);
                *(float2*)&g_h[(size_t)r1 * HH + col] = v;
            }
        }
    }
}

// ---------------------------------------------------------------------------
// Pull + finalize fused: one warp per node; 2-edge unroll for MLP.
// ---------------------------------------------------------------------------
__global__ void pull_kernel(float* __restrict__ out,
                            const float* __restrict__ b,
                            const float* __restrict__ alpha,
                            int n) {
    int warp = (blockIdx.x * blockDim.x + threadIdx.x) >> 5;
    int lane = threadIdx.x & 31;
    if (warp >= n) return;
    int node = warp;
    int beg = g_rowptr[node];
    int end = g_rowptr[node + 1];

    const float4* self = (const float4*)&g_h[(size_t)node * HH];
    float4 acc[4];
#pragma unroll
    for (int i = 0; i < 4; i++) acc[i] = self[lane + i * 32];

    int e = beg;
    for (; e + 1 < end; e += 2) {
        int r0 = g_srcidx[e];
        int r1 = g_srcidx[e + 1];
        const float4* s0 = (const float4*)&g_h[(size_t)r0 * HH];
        const float4* s1 = (const float4*)&g_h[(size_t)r1 * HH];
        float4 v0[4], v1[4];
#pragma unroll
        for (int i = 0; i < 4; i++) v0[i] = s0[lane + i * 32];
#pragma unroll
        for (int i = 0; i < 4; i++) v1[i] = s1[lane + i * 32];
#pragma unroll
        for (int i = 0; i < 4; i++) {
            acc[i].x += v0[i].x + v1[i].x;
            acc[i].y += v0[i].y + v1[i].y;
            acc[i].z += v0[i].z + v1[i].z;
            acc[i].w += v0[i].w + v1[i].w;
        }
    }
    if (e < end) {
        int r0 = g_srcidx[e];
        const float4* s0 = (const float4*)&g_h[(size_t)r0 * HH];
#pragma unroll
        for (int i = 0; i < 4; i++) {
            float4 v = s0[lane + i * 32];
            acc[i].x += v.x; acc[i].y += v.y; acc[i].z += v.z; acc[i].w += v.w;
        }
    }

    float s = g_dinv[node];
    float* dst = &out[(size_t)node * HH];
#pragma unroll
    for (int i = 0; i < 4; i++) {
        int c4 = lane + i * 32;
        float4 bb = *(const float4*)&b[c4 * 4];
        float4 aa = *(const float4*)&alpha[c4 * 4];
        float4 v = acc[i];
        v.x = v.x * s + bb.x;  v.x = v.x > 0.f ? v.x : aa.x * v.x;
        v.y = v.y * s + bb.y;  v.y = v.y > 0.f ? v.y : aa.y * v.y;
        v.z = v.z * s + bb.z;  v.z = v.z > 0.f ? v.z : aa.z * v.z;
        v.w = v.w * s + bb.w;  v.w = v.w > 0.f ? v.w : aa.w * v.w;
        *(float4*)&dst[c4 * 4] = v;
    }
}

// ---------------------------------------------------------------------------
// Launch
// ---------------------------------------------------------------------------
extern "C" void kernel_launch(void* const* d_in, const int* in_sizes, int n_in,
                              void* d_out, int out_size) {
    const float* x     = (const float*)d_in[0];  // [N, 128]
    const int*   ei    = (const int*)d_in[1];    // [2, E] int32
    const float* W     = (const float*)d_in[2];  // [512, 128]
    const float* b     = (const float*)d_in[3];  // [512]
    const float* alpha = (const float*)d_in[4];  // [512]
    float*       out   = (float*)d_out;          // [N, 512]

    const int N = in_sizes[0] / FF;
    const int E = in_sizes[1] / 2;
    const int nb = (N + SCAN_B - 1) / SCAN_B;

    cudaFuncSetAttribute(tf32_gemm_kernel,
                         cudaFuncAttributeMaxDynamicSharedMemorySize,
                         SMEM_TOTAL_GEMM);

    // 1) CSR build (by target) + dinv (fused into scan)
    count_kernel<<<(E + 255) / 256, 256>>>(ei, E, N);
    scan_block_kernel<<<nb, SCAN_B>>>(N);
    scan_sums_kernel<<<1, 256>>>(nb);
    add_off_kernel<<<(N + 255) / 256, 256>>>(N, E);
    fill_kernel<<<(E + 255) / 256, 256>>>(ei, E, N);

    // 2) g_h = (x @ W^T) * dinv[row]  — tf32 TC, 2D tiled, double-buffered
    dim3 gemm_grid(HH / 128, (N + 127) / 128);
    tf32_gemm_kernel<<<gemm_grid, 256, SMEM_TOTAL_GEMM>>>(x, W, N);

    // 3) pull-based aggregate + finalize (warp per node)
    int warps_per_block = 256 / 32;
    pull_kernel<<<(N + warps_per_block - 1) / warps_per_block, 256>>>(out, b, alpha, N);
}

// round 9
// speedup vs baseline: 1.1453x; 1.1453x over previous
#include <cuda_runtime.h>
#include <cuda_fp16.h>
#include <cstdint>

#define FF 128
#define HH 512
#define HH2 256   // half2 per row
#define MAXN 50048
#define MAXE 401408
#define SCAN_B 1024

// Scratch (static device globals — no runtime allocation allowed)
__device__ __align__(16) uint32_t g_h[(size_t)50000 * HH2];  // h' rows in fp16 (half2-packed)
__device__ int   g_cnt[MAXN];               // zero at load; re-zeroed by scan each run
__device__ float g_dinv[MAXN];
__device__ int   g_rowptr[MAXN + 1];
__device__ int   g_cur[MAXN];
__device__ int   g_srcidx[MAXE];
__device__ int   g_bsum[256];
__device__ int   g_boff[256];

// ---------------------------------------------------------------------------
// CSR build: count -> scan(+dinv, +re-zero) -> add_off -> fill
// ---------------------------------------------------------------------------
__global__ void count_kernel(const int* __restrict__ ei, int E, int n) {
    int e = blockIdx.x * blockDim.x + threadIdx.x;
    if (e < E) {
        int c = ei[E + e];
        if ((unsigned)c < (unsigned)n) atomicAdd(&g_cnt[c], 1);
    }
}

__global__ void scan_block_kernel(int n) {
    __shared__ int sh[SCAN_B];
    int gid = blockIdx.x * SCAN_B + threadIdx.x;
    int v = 0;
    if (gid < n) {
        v = g_cnt[gid];
        g_cnt[gid] = 0;                           // restore zeros for replay determinism
        g_dinv[gid] = rsqrtf((float)(v + 1));     // +1 self-loop
    }
    sh[threadIdx.x] = v;
    __syncthreads();
#pragma unroll
    for (int off = 1; off < SCAN_B; off <<= 1) {
        int t = (threadIdx.x >= off) ? sh[threadIdx.x - off] : 0;
        __syncthreads();
        sh[threadIdx.x] += t;
        __syncthreads();
    }
    if (gid < n) g_rowptr[gid] = sh[threadIdx.x] - v;   // exclusive
    if (threadIdx.x == SCAN_B - 1) g_bsum[blockIdx.x] = sh[threadIdx.x];
}

__global__ void scan_sums_kernel(int nb) {
    __shared__ int sh[256];
    int v = (threadIdx.x < nb) ? g_bsum[threadIdx.x] : 0;
    sh[threadIdx.x] = v;
    __syncthreads();
#pragma unroll
    for (int off = 1; off < 256; off <<= 1) {
        int t = (threadIdx.x >= off) ? sh[threadIdx.x - off] : 0;
        __syncthreads();
        sh[threadIdx.x] += t;
        __syncthreads();
    }
    if (threadIdx.x < nb) g_boff[threadIdx.x] = sh[threadIdx.x] - v;  // exclusive
}

__global__ void add_off_kernel(int n, int E) {
    int i = blockIdx.x * blockDim.x + threadIdx.x;
    if (i < n) {
        int v = g_rowptr[i] + g_boff[i / SCAN_B];
        g_rowptr[i] = v;
        g_cur[i] = v;
    }
    if (i == 0) g_rowptr[n] = E;
}

__global__ void fill_kernel(const int* __restrict__ ei, int E, int n) {
    int e = blockIdx.x * blockDim.x + threadIdx.x;
    if (e < E) {
        int r = ei[e];
        int c = ei[E + e];
        if ((unsigned)r < (unsigned)n && (unsigned)c < (unsigned)n) {
            int pos = atomicAdd(&g_cur[c], 1);
            g_srcidx[pos] = r;
        }
    }
}

// ---------------------------------------------------------------------------
// tf32 tensor-core GEMM, A-resident + cp.async double-buffered B (round-7 best).
// Output stored as fp16 (half2) with dinv[row] scaling.
// ---------------------------------------------------------------------------
#define AS_LD 132
#define BS_LD 36
#define AS_BYTES (128 * AS_LD * 4)            // 67584
#define BS_BYTES (2 * 128 * BS_LD * 4)        // 36864
#define SMEM_TOTAL_GEMM (AS_BYTES + BS_BYTES) // 104448

__device__ __forceinline__ uint32_t f2tf(float x) {
    uint32_t u;
    asm("cvt.rna.tf32.f32 %0, %1;" : "=r"(u) : "f"(x));
    return u;
}

__device__ __forceinline__ void mma8(float* c, const uint32_t* a,
                                     uint32_t b0, uint32_t b1) {
    asm volatile(
        "mma.sync.aligned.m16n8k8.row.col.f32.tf32.tf32.f32 "
        "{%0,%1,%2,%3}, {%4,%5,%6,%7}, {%8,%9}, {%0,%1,%2,%3};"
        : "+f"(c[0]), "+f"(c[1]), "+f"(c[2]), "+f"(c[3])
        : "r"(a[0]), "r"(a[1]), "r"(a[2]), "r"(a[3]), "r"(b0), "r"(b1));
}

__device__ __forceinline__ void cp_async16(void* sptr, const void* gptr) {
    uint32_t sa = (uint32_t)__cvta_generic_to_shared(sptr);
    asm volatile("cp.async.cg.shared.global [%0], [%1], 16;" :: "r"(sa), "l"(gptr));
}
__device__ __forceinline__ void cp_commit() {
    asm volatile("cp.async.commit_group;");
}
template <int NN>
__device__ __forceinline__ void cp_wait() {
    asm volatile("cp.async.wait_group %0;" :: "n"(NN));
}

__global__ __launch_bounds__(256) void tf32_gemm_kernel(
        const float* __restrict__ X, const float* __restrict__ W, int M) {
    extern __shared__ char smem_raw[];
    uint32_t (*As)[AS_LD]       = (uint32_t(*)[AS_LD])smem_raw;
    float    (*Bs)[128][BS_LD]  = (float(*)[128][BS_LD])(smem_raw + AS_BYTES);

    const int t    = threadIdx.x;
    const int wid  = t >> 5;
    const int lane = t & 31;
    const int warp_m = wid & 3;
    const int warp_n = wid >> 2;
    const int bm = blockIdx.x * 128;

    // ---- load full A tile (128 rows x 128 k), convert to tf32 ----
#pragma unroll
    for (int i = 0; i < 16; i++) {
        int idx = t + i * 256;
        int row = idx >> 5;
        int c4  = idx & 31;
        int gm  = bm + row;
        float4 v = make_float4(0.f, 0.f, 0.f, 0.f);
        if (gm < M) v = *(const float4*)&X[(size_t)gm * FF + c4 * 4];
        uint32_t* s = &As[row][c4 * 4];
        s[0] = f2tf(v.x); s[1] = f2tf(v.y); s[2] = f2tf(v.z); s[3] = f2tf(v.w);
    }

    auto issueB = [&](int s, int buf) {
        int nt = s >> 2, kt = s & 3;
#pragma unroll
        for (int i = 0; i < 4; i++) {
            int idx = t + i * 256;
            int row = idx >> 3;
            int c4  = idx & 7;
            cp_async16(&Bs[buf][row][c4 * 4],
                       &W[(size_t)(nt * 128 + row) * FF + kt * 32 + c4 * 4]);
        }
        cp_commit();
    };

    issueB(0, 0);
    __syncthreads();

    float c[2][8][4];
#pragma unroll
    for (int mt = 0; mt < 2; mt++)
#pragma unroll
        for (int j = 0; j < 8; j++)
#pragma unroll
            for (int q = 0; q < 4; q++) c[mt][j][q] = 0.f;

    const int fr = lane >> 2;
    const int fc = lane & 3;

    for (int s = 0; s < 16; s++) {
        int buf = s & 1;
        if (s < 15) { issueB(s + 1, buf ^ 1); cp_wait<1>(); }
        else        { cp_wait<0>(); }
        __syncthreads();

        const int kt = s & 3;
#pragma unroll
        for (int ks = 0; ks < 4; ks++) {
            const int kcA = kt * 32 + ks * 8 + fc;
            const int kcB = ks * 8 + fc;
            uint32_t a[2][4];
#pragma unroll
            for (int mt = 0; mt < 2; mt++) {
                int r = warp_m * 32 + mt * 16 + fr;
                a[mt][0] = As[r][kcA];
                a[mt][1] = As[r + 8][kcA];
                a[mt][2] = As[r][kcA + 4];
                a[mt][3] = As[r + 8][kcA + 4];
            }
#pragma unroll
            for (int j = 0; j < 8; j++) {
                int nr = warp_n * 64 + j * 8 + fr;
                uint32_t b0 = f2tf(Bs[buf][nr][kcB]);
                uint32_t b1 = f2tf(Bs[buf][nr][kcB + 4]);
#pragma unroll
                for (int mt = 0; mt < 2; mt++)
                    mma8(c[mt][j], a[mt], b0, b1);
            }
        }
        __syncthreads();

        if ((s & 3) == 3) {
            int nt = s >> 2;
#pragma unroll
            for (int mt = 0; mt < 2; mt++) {
                int r0 = bm + warp_m * 32 + mt * 16 + fr;
                int r1 = r0 + 8;
                float s0 = (r0 < M) ? g_dinv[r0] : 0.f;
                float s1 = (r1 < M) ? g_dinv[r1] : 0.f;
#pragma unroll
                for (int j = 0; j < 8; j++) {
                    int colh = nt * 64 + warp_n * 32 + j * 4 + fc;  // half2 index
                    if (r0 < M) {
                        __half2 h = __floats2half2_rn(c[mt][j][0] * s0, c[mt][j][1] * s0);
                        *(__half2*)&g_h[(size_t)r0 * HH2 + colh] = h;
                    }
                    if (r1 < M) {
                        __half2 h = __floats2half2_rn(c[mt][j][2] * s1, c[mt][j][3] * s1);
                        *(__half2*)&g_h[(size_t)r1 * HH2 + colh] = h;
                    }
#pragma unroll
                    for (int q = 0; q < 4; q++) c[mt][j][q] = 0.f;
                }
            }
        }
    }
}

// ---------------------------------------------------------------------------
// Pull + finalize fused: one warp per node; fp16 gather, fp32 accumulate.
// Each row = 256 half2 = 64 uint4; lane handles uint4 chunks lane, lane+32.
// ---------------------------------------------------------------------------
__device__ __forceinline__ void acc_uint4(float2* acc, uint4 v) {
    float2 f;
    f = __half22float2(*(__half2*)&v.x); acc[0].x += f.x; acc[0].y += f.y;
    f = __half22float2(*(__half2*)&v.y); acc[1].x += f.x; acc[1].y += f.y;
    f = __half22float2(*(__half2*)&v.z); acc[2].x += f.x; acc[2].y += f.y;
    f = __half22float2(*(__half2*)&v.w); acc[3].x += f.x; acc[3].y += f.y;
}

__global__ void pull_kernel(float* __restrict__ out,
                            const float* __restrict__ b,
                            const float* __restrict__ alpha,
                            int n) {
    int warp = (blockIdx.x * blockDim.x + threadIdx.x) >> 5;
    int lane = threadIdx.x & 31;
    if (warp >= n) return;
    int node = warp;
    int beg = g_rowptr[node];
    int end = g_rowptr[node + 1];

    const uint4* self = (const uint4*)&g_h[(size_t)node * HH2];
    float2 acc[2][4];
#pragma unroll
    for (int i = 0; i < 2; i++) {
        uint4 v = self[lane + i * 32];
        float2 f;
        f = __half22float2(*(__half2*)&v.x); acc[i][0] = f;
        f = __half22float2(*(__half2*)&v.y); acc[i][1] = f;
        f = __half22float2(*(__half2*)&v.z); acc[i][2] = f;
        f = __half22float2(*(__half2*)&v.w); acc[i][3] = f;
    }

    int e = beg;
    for (; e + 1 < end; e += 2) {
        int r0 = g_srcidx[e];
        int r1 = g_srcidx[e + 1];
        const uint4* s0 = (const uint4*)&g_h[(size_t)r0 * HH2];
        const uint4* s1 = (const uint4*)&g_h[(size_t)r1 * HH2];
        uint4 v00 = s0[lane];        uint4 v01 = s0[lane + 32];
        uint4 v10 = s1[lane];        uint4 v11 = s1[lane + 32];
        acc_uint4(acc[0], v00); acc_uint4(acc[1], v01);
        acc_uint4(acc[0], v10); acc_uint4(acc[1], v11);
    }
    if (e < end) {
        int r0 = g_srcidx[e];
        const uint4* s0 = (const uint4*)&g_h[(size_t)r0 * HH2];
        acc_uint4(acc[0], s0[lane]);
        acc_uint4(acc[1], s0[lane + 32]);
    }

    float s = g_dinv[node];
    float* dst = &out[(size_t)node * HH];
#pragma unroll
    for (int i = 0; i < 2; i++) {
#pragma unroll
        for (int j = 0; j < 4; j++) {
            int colh = (lane + i * 32) * 4 + j;   // half2/float2 index within row
            float2 bb = ((const float2*)b)[colh];
            float2 aa = ((const float2*)alpha)[colh];
            float2 v = acc[i][j];
            v.x = v.x * s + bb.x;  v.x = v.x > 0.f ? v.x : aa.x * v.x;
            v.y = v.y * s + bb.y;  v.y = v.y > 0.f ? v.y : aa.y * v.y;
            ((float2*)dst)[colh] = v;
        }
    }
}

// ---------------------------------------------------------------------------
// Launch
// ---------------------------------------------------------------------------
extern "C" void kernel_launch(void* const* d_in, const int* in_sizes, int n_in,
                              void* d_out, int out_size) {
    const float* x     = (const float*)d_in[0];  // [N, 128]
    const int*   ei    = (const int*)d_in[1];    // [2, E] int32
    const float* W     = (const float*)d_in[2];  // [512, 128]
    const float* b     = (const float*)d_in[3];  // [512]
    const float* alpha = (const float*)d_in[4];  // [512]
    float*       out   = (float*)d_out;          // [N, 512]

    const int N = in_sizes[0] / FF;
    const int E = in_sizes[1] / 2;
    const int nb = (N + SCAN_B - 1) / SCAN_B;

    cudaFuncSetAttribute(tf32_gemm_kernel,
                         cudaFuncAttributeMaxDynamicSharedMemorySize,
                         SMEM_TOTAL_GEMM);

    // 1) CSR build (by target) + dinv (fused into scan)
    count_kernel<<<(E + 255) / 256, 256>>>(ei, E, N);
    scan_block_kernel<<<nb, SCAN_B>>>(N);
    scan_sums_kernel<<<1, 256>>>(nb);
    add_off_kernel<<<(N + 255) / 256, 256>>>(N, E);
    fill_kernel<<<(E + 255) / 256, 256>>>(ei, E, N);

    // 2) g_h = fp16((x @ W^T) * dinv[row]) — tf32 TC, A-resident, async B pipe
    tf32_gemm_kernel<<<(N + 127) / 128, 256, SMEM_TOTAL_GEMM>>>(x, W, N);

    // 3) pull-based aggregate + finalize (warp per node)
    int warps_per_block = 256 / 32;
    pull_kernel<<<(N + warps_per_block - 1) / warps_per_block, 256>>>(out, b, alpha, N);
}

// round 10
// speedup vs baseline: 1.3269x; 1.1586x over previous
#include <cuda_runtime.h>
#include <cuda_fp16.h>
#include <cstdint>

#define FF 128
#define HH 512
#define HH2 256   // half2 per row
#define MAXN 50048
#define MAXE 401408
#define SCAN_B 1024

// Scratch (static device globals — no runtime allocation allowed)
__device__ __align__(16) uint32_t g_h[(size_t)50000 * HH2];  // h' rows fp16 (half2)
__device__ __align__(16) uint32_t g_wh[512 * 64];            // W in fp16 (half2), [512][64]
__device__ int   g_cnt[MAXN];
__device__ float g_dinv[MAXN];
__device__ int   g_rowptr[MAXN + 1];
__device__ int   g_cur[MAXN];
__device__ int   g_srcidx[MAXE];
__device__ int   g_bsum[256];
__device__ int   g_boff[256];

// ---------------------------------------------------------------------------
// W -> fp16 prep (512x128 floats -> half2 packed)
// ---------------------------------------------------------------------------
__global__ void wprep_kernel(const float* __restrict__ W) {
    int i = blockIdx.x * blockDim.x + threadIdx.x;   // half2 index, 32768 total
    if (i < 512 * 64) {
        float2 v = ((const float2*)W)[i];
        __half2 h = __floats2half2_rn(v.x, v.y);
        g_wh[i] = *(uint32_t*)&h;
    }
}

// ---------------------------------------------------------------------------
// CSR build: count -> scan(+dinv, +re-zero) -> add_off -> fill
// ---------------------------------------------------------------------------
__global__ void count_kernel(const int* __restrict__ ei, int E, int n) {
    int e = blockIdx.x * blockDim.x + threadIdx.x;
    if (e < E) {
        int c = ei[E + e];
        if ((unsigned)c < (unsigned)n) atomicAdd(&g_cnt[c], 1);
    }
}

__global__ void scan_block_kernel(int n) {
    __shared__ int sh[SCAN_B];
    int gid = blockIdx.x * SCAN_B + threadIdx.x;
    int v = 0;
    if (gid < n) {
        v = g_cnt[gid];
        g_cnt[gid] = 0;
        g_dinv[gid] = rsqrtf((float)(v + 1));
    }
    sh[threadIdx.x] = v;
    __syncthreads();
#pragma unroll
    for (int off = 1; off < SCAN_B; off <<= 1) {
        int t = (threadIdx.x >= off) ? sh[threadIdx.x - off] : 0;
        __syncthreads();
        sh[threadIdx.x] += t;
        __syncthreads();
    }
    if (gid < n) g_rowptr[gid] = sh[threadIdx.x] - v;
    if (threadIdx.x == SCAN_B - 1) g_bsum[blockIdx.x] = sh[threadIdx.x];
}

__global__ void scan_sums_kernel(int nb) {
    __shared__ int sh[256];
    int v = (threadIdx.x < nb) ? g_bsum[threadIdx.x] : 0;
    sh[threadIdx.x] = v;
    __syncthreads();
#pragma unroll
    for (int off = 1; off < 256; off <<= 1) {
        int t = (threadIdx.x >= off) ? sh[threadIdx.x - off] : 0;
        __syncthreads();
        sh[threadIdx.x] += t;
        __syncthreads();
    }
    if (threadIdx.x < nb) g_boff[threadIdx.x] = sh[threadIdx.x] - v;
}

__global__ void add_off_kernel(int n, int E) {
    int i = blockIdx.x * blockDim.x + threadIdx.x;
    if (i < n) {
        int v = g_rowptr[i] + g_boff[i / SCAN_B];
        g_rowptr[i] = v;
        g_cur[i] = v;
    }
    if (i == 0) g_rowptr[n] = E;
}

__global__ void fill_kernel(const int* __restrict__ ei, int E, int n) {
    int e = blockIdx.x * blockDim.x + threadIdx.x;
    if (e < E) {
        int r = ei[e];
        int c = ei[E + e];
        if ((unsigned)r < (unsigned)n && (unsigned)c < (unsigned)n) {
            int pos = atomicAdd(&g_cur[c], 1);
            g_srcidx[pos] = r;
        }
    }
}

// ---------------------------------------------------------------------------
// fp16 tensor-core GEMM (m16n8k16), A-resident + cp.async double-buffered B.
//   As: [128][68] half2  (full K=128 -> 64 half2/row, pad 4)   34816 B
//   Bs: [2][128][20] half2 (one 32-k tile = 16 half2/row, pad 4) 20480 B
// ---------------------------------------------------------------------------
#define AS_LDH 68
#define BS_LDH 20
#define AS_BYTESH (128 * AS_LDH * 4)
#define BS_BYTESH (2 * 128 * BS_LDH * 4)
#define SMEM_TOTAL_GEMM (AS_BYTESH + BS_BYTESH)   // 55296

__device__ __forceinline__ void mma16(float* c, const uint32_t* a,
                                      uint32_t b0, uint32_t b1) {
    asm volatile(
        "mma.sync.aligned.m16n8k16.row.col.f32.f16.f16.f32 "
        "{%0,%1,%2,%3}, {%4,%5,%6,%7}, {%8,%9}, {%0,%1,%2,%3};"
        : "+f"(c[0]), "+f"(c[1]), "+f"(c[2]), "+f"(c[3])
        : "r"(a[0]), "r"(a[1]), "r"(a[2]), "r"(a[3]), "r"(b0), "r"(b1));
}

__device__ __forceinline__ void cp_async16(void* sptr, const void* gptr) {
    uint32_t sa = (uint32_t)__cvta_generic_to_shared(sptr);
    asm volatile("cp.async.cg.shared.global [%0], [%1], 16;" :: "r"(sa), "l"(gptr));
}
__device__ __forceinline__ void cp_commit() {
    asm volatile("cp.async.commit_group;");
}
template <int NN>
__device__ __forceinline__ void cp_wait() {
    asm volatile("cp.async.wait_group %0;" :: "n"(NN));
}

__global__ __launch_bounds__(256) void fp16_gemm_kernel(
        const float* __restrict__ X, int M) {
    extern __shared__ char smem_raw[];
    uint32_t (*As)[AS_LDH]      = (uint32_t(*)[AS_LDH])smem_raw;
    uint32_t (*Bs)[128][BS_LDH] = (uint32_t(*)[128][BS_LDH])(smem_raw + AS_BYTESH);

    const int t    = threadIdx.x;
    const int wid  = t >> 5;
    const int lane = t & 31;
    const int warp_m = wid & 3;
    const int warp_n = wid >> 2;
    const int bm = blockIdx.x * 128;
    const int fr = lane >> 2;
    const int fc = lane & 3;

    // ---- load full A tile (128 rows x 128 k) fp32 -> fp16 half2 ----
#pragma unroll
    for (int i = 0; i < 16; i++) {
        int idx = t + i * 256;
        int row = idx >> 5;             // 0..127
        int c4  = idx & 31;             // float4 col 0..31
        int gm  = bm + row;
        float4 v = make_float4(0.f, 0.f, 0.f, 0.f);
        if (gm < M) v = *(const float4*)&X[(size_t)gm * FF + c4 * 4];
        __half2 h0 = __floats2half2_rn(v.x, v.y);
        __half2 h1 = __floats2half2_rn(v.z, v.w);
        As[row][c4 * 2]     = *(uint32_t*)&h0;
        As[row][c4 * 2 + 1] = *(uint32_t*)&h1;
    }

    // B tile s: nt = s>>2 (N-block of 128), kt = s&3 (32-k block).
    // Each row: 16 half2 = 64 B = 4 x 16B chunks. 512 chunks, 2 per thread.
    auto issueB = [&](int s, int buf) {
        int nt = s >> 2, kt = s & 3;
#pragma unroll
        for (int i = 0; i < 2; i++) {
            int idx = t + i * 256;      // 0..511
            int row = idx >> 2;         // 0..127
            int c16 = idx & 3;          // 16B chunk
            cp_async16(&Bs[buf][row][c16 * 4],
                       &g_wh[(size_t)(nt * 128 + row) * 64 + kt * 16 + c16 * 4]);
        }
        cp_commit();
    };

    issueB(0, 0);
    __syncthreads();

    float c[2][8][4];
#pragma unroll
    for (int mt = 0; mt < 2; mt++)
#pragma unroll
        for (int j = 0; j < 8; j++)
#pragma unroll
            for (int q = 0; q < 4; q++) c[mt][j][q] = 0.f;

    for (int s = 0; s < 16; s++) {
        int buf = s & 1;
        if (s < 15) { issueB(s + 1, buf ^ 1); cp_wait<1>(); }
        else        { cp_wait<0>(); }
        __syncthreads();

        const int kt = s & 3;
#pragma unroll
        for (int ks = 0; ks < 2; ks++) {            // two k16 steps per 32-k tile
            const int kcA = kt * 16 + ks * 8 + fc;  // half2 col in As
            const int kcB = ks * 8 + fc;            // half2 col in Bs tile
            uint32_t a[2][4];
#pragma unroll
            for (int mt = 0; mt < 2; mt++) {
                int r = warp_m * 32 + mt * 16 + fr;
                a[mt][0] = As[r][kcA];
                a[mt][1] = As[r + 8][kcA];
                a[mt][2] = As[r][kcA + 4];
                a[mt][3] = As[r + 8][kcA + 4];
            }
#pragma unroll
            for (int j = 0; j < 8; j++) {
                int nr = warp_n * 64 + j * 8 + fr;
                uint32_t b0 = Bs[buf][nr][kcB];
                uint32_t b1 = Bs[buf][nr][kcB + 4];
#pragma unroll
                for (int mt = 0; mt < 2; mt++)
                    mma16(c[mt][j], a[mt], b0, b1);
            }
        }
        __syncthreads();

        if ((s & 3) == 3) {
            int nt = s >> 2;
#pragma unroll
            for (int mt = 0; mt < 2; mt++) {
                int r0 = bm + warp_m * 32 + mt * 16 + fr;
                int r1 = r0 + 8;
                float s0 = (r0 < M) ? g_dinv[r0] : 0.f;
                float s1 = (r1 < M) ? g_dinv[r1] : 0.f;
#pragma unroll
                for (int j = 0; j < 8; j++) {
                    int colh = nt * 64 + warp_n * 32 + j * 4 + fc;  // half2 col
                    if (r0 < M) {
                        __half2 h = __floats2half2_rn(c[mt][j][0] * s0, c[mt][j][1] * s0);
                        g_h[(size_t)r0 * HH2 + colh] = *(uint32_t*)&h;
                    }
                    if (r1 < M) {
                        __half2 h = __floats2half2_rn(c[mt][j][2] * s1, c[mt][j][3] * s1);
                        g_h[(size_t)r1 * HH2 + colh] = *(uint32_t*)&h;
                    }
#pragma unroll
                    for (int q = 0; q < 4; q++) c[mt][j][q] = 0.f;
                }
            }
        }
    }
}

// ---------------------------------------------------------------------------
// Pull + finalize fused: one warp per node; fp16 gather (4-edge unroll),
// fp32 accumulate. Row = 64 uint4; lane handles chunks lane, lane+32.
// ---------------------------------------------------------------------------
__device__ __forceinline__ void acc_uint4(float2* acc, uint4 v) {
    float2 f;
    f = __half22float2(*(__half2*)&v.x); acc[0].x += f.x; acc[0].y += f.y;
    f = __half22float2(*(__half2*)&v.y); acc[1].x += f.x; acc[1].y += f.y;
    f = __half22float2(*(__half2*)&v.z); acc[2].x += f.x; acc[2].y += f.y;
    f = __half22float2(*(__half2*)&v.w); acc[3].x += f.x; acc[3].y += f.y;
}

__global__ void pull_kernel(float* __restrict__ out,
                            const float* __restrict__ b,
                            const float* __restrict__ alpha,
                            int n) {
    int warp = (blockIdx.x * blockDim.x + threadIdx.x) >> 5;
    int lane = threadIdx.x & 31;
    if (warp >= n) return;
    int node = warp;
    int beg = g_rowptr[node];
    int end = g_rowptr[node + 1];

    const uint4* self = (const uint4*)&g_h[(size_t)node * HH2];
    float2 acc[2][4];
#pragma unroll
    for (int i = 0; i < 2; i++) {
        uint4 v = self[lane + i * 32];
        acc[i][0] = __half22float2(*(__half2*)&v.x);
        acc[i][1] = __half22float2(*(__half2*)&v.y);
        acc[i][2] = __half22float2(*(__half2*)&v.z);
        acc[i][3] = __half22float2(*(__half2*)&v.w);
    }

    int e = beg;
    for (; e + 3 < end; e += 4) {
        int r0 = g_srcidx[e];
        int r1 = g_srcidx[e + 1];
        int r2 = g_srcidx[e + 2];
        int r3 = g_srcidx[e + 3];
        const uint4* s0 = (const uint4*)&g_h[(size_t)r0 * HH2];
        const uint4* s1 = (const uint4*)&g_h[(size_t)r1 * HH2];
        const uint4* s2 = (const uint4*)&g_h[(size_t)r2 * HH2];
        const uint4* s3 = (const uint4*)&g_h[(size_t)r3 * HH2];
        uint4 v00 = s0[lane], v01 = s0[lane + 32];
        uint4 v10 = s1[lane], v11 = s1[lane + 32];
        uint4 v20 = s2[lane], v21 = s2[lane + 32];
        uint4 v30 = s3[lane], v31 = s3[lane + 32];
        acc_uint4(acc[0], v00); acc_uint4(acc[1], v01);
        acc_uint4(acc[0], v10); acc_uint4(acc[1], v11);
        acc_uint4(acc[0], v20); acc_uint4(acc[1], v21);
        acc_uint4(acc[0], v30); acc_uint4(acc[1], v31);
    }
    for (; e < end; e++) {
        int r0 = g_srcidx[e];
        const uint4* s0 = (const uint4*)&g_h[(size_t)r0 * HH2];
        acc_uint4(acc[0], s0[lane]);
        acc_uint4(acc[1], s0[lane + 32]);
    }

    float s = g_dinv[node];
    float* dst = &out[(size_t)node * HH];
#pragma unroll
    for (int i = 0; i < 2; i++) {
#pragma unroll
        for (int j = 0; j < 4; j++) {
            int colh = (lane + i * 32) * 4 + j;
            float2 bb = ((const float2*)b)[colh];
            float2 aa = ((const float2*)alpha)[colh];
            float2 v = acc[i][j];
            v.x = v.x * s + bb.x;  v.x = v.x > 0.f ? v.x : aa.x * v.x;
            v.y = v.y * s + bb.y;  v.y = v.y > 0.f ? v.y : aa.y * v.y;
            ((float2*)dst)[colh] = v;
        }
    }
}

// ---------------------------------------------------------------------------
// Launch
// ---------------------------------------------------------------------------
extern "C" void kernel_launch(void* const* d_in, const int* in_sizes, int n_in,
                              void* d_out, int out_size) {
    const float* x     = (const float*)d_in[0];  // [N, 128]
    const int*   ei    = (const int*)d_in[1];    // [2, E] int32
    const float* W     = (const float*)d_in[2];  // [512, 128]
    const float* b     = (const float*)d_in[3];  // [512]
    const float* alpha = (const float*)d_in[4];  // [512]
    float*       out   = (float*)d_out;          // [N, 512]

    const int N = in_sizes[0] / FF;
    const int E = in_sizes[1] / 2;
    const int nb = (N + SCAN_B - 1) / SCAN_B;

    cudaFuncSetAttribute(fp16_gemm_kernel,
                         cudaFuncAttributeMaxDynamicSharedMemorySize,
                         SMEM_TOTAL_GEMM);

    // 0) W -> fp16
    wprep_kernel<<<(512 * 64 + 255) / 256, 256>>>(W);

    // 1) CSR build (by target) + dinv (fused into scan)
    count_kernel<<<(E + 255) / 256, 256>>>(ei, E, N);
    scan_block_kernel<<<nb, SCAN_B>>>(N);
    scan_sums_kernel<<<1, 256>>>(nb);
    add_off_kernel<<<(N + 255) / 256, 256>>>(N, E);
    fill_kernel<<<(E + 255) / 256, 256>>>(ei, E, N);

    // 2) g_h = fp16((x @ W^T) * dinv[row]) — fp16 TC, A-resident, async B pipe
    fp16_gemm_kernel<<<(N + 127) / 128, 256, SMEM_TOTAL_GEMM>>>(x, N);

    // 3) pull-based aggregate + finalize (warp per node)
    int warps_per_block = 256 / 32;
    pull_kernel<<<(N + warps_per_block - 1) / warps_per_block, 256>>>(out, b, alpha, N);
}

// round 11
// speedup vs baseline: 1.3614x; 1.0260x over previous
#include <cuda_runtime.h>
#include <cuda_fp16.h>
#include <cstdint>

#define FF 128
#define HH 512
#define HH2 256   // half2 per row
#define MAXN 50048
#define MAXE 401408
#define SCAN_B 1024

// Scratch (static device globals — no runtime allocation allowed)
__device__ __align__(16) uint32_t g_h[(size_t)50000 * HH2];  // h' rows fp16 (half2)
__device__ __align__(16) uint32_t g_wh[512 * 64];            // W fp16 (half2), [512][64]
__device__ int   g_cnt[MAXN];
__device__ float g_dinv[MAXN];
__device__ int   g_rowptr[MAXN + 1];
__device__ int   g_cur[MAXN];
__device__ int   g_srcidx[MAXE];
__device__ int   g_bsum[256];

// ---------------------------------------------------------------------------
// count (edge targets) + W->fp16 prep, fused via grid partition
// ---------------------------------------------------------------------------
__global__ void count_wprep_kernel(const int* __restrict__ ei,
                                   const float* __restrict__ W,
                                   int E, int n, int countBlocks) {
    int bid = blockIdx.x;
    if (bid < countBlocks) {
        int e = bid * 256 + threadIdx.x;
        if (e < E) {
            int c = ei[E + e];
            if ((unsigned)c < (unsigned)n) atomicAdd(&g_cnt[c], 1);
        }
    } else {
        int i = (bid - countBlocks) * 256 + threadIdx.x;   // half2 index
        if (i < 512 * 64) {
            float2 v = ((const float2*)W)[i];
            __half2 h = __floats2half2_rn(v.x, v.y);
            g_wh[i] = *(uint32_t*)&h;
        }
    }
}

// Per-block scan; also computes dinv and re-zeroes g_cnt for replay determinism
__global__ void scan_block_kernel(int n) {
    __shared__ int sh[SCAN_B];
    int gid = blockIdx.x * SCAN_B + threadIdx.x;
    int v = 0;
    if (gid < n) {
        v = g_cnt[gid];
        g_cnt[gid] = 0;
        g_dinv[gid] = rsqrtf((float)(v + 1));
    }
    sh[threadIdx.x] = v;
    __syncthreads();
#pragma unroll
    for (int off = 1; off < SCAN_B; off <<= 1) {
        int t = (threadIdx.x >= off) ? sh[threadIdx.x - off] : 0;
        __syncthreads();
        sh[threadIdx.x] += t;
        __syncthreads();
    }
    if (gid < n) g_rowptr[gid] = sh[threadIdx.x] - v;
    if (threadIdx.x == SCAN_B - 1) g_bsum[blockIdx.x] = sh[threadIdx.x];
}

// add block offsets; the 49-entry block-sum prefix is recomputed per block (cheap)
__global__ void add_off_kernel(int n, int E, int nb) {
    __shared__ int soff[64];
    if (threadIdx.x < 64) {
        int s = 0;
        for (int j = 0; j < (int)threadIdx.x && j < nb; j++) s += g_bsum[j];
        soff[threadIdx.x] = s;
    }
    __syncthreads();
    int i = blockIdx.x * blockDim.x + threadIdx.x;
    if (i < n) {
        int v = g_rowptr[i] + soff[i / SCAN_B];
        g_rowptr[i] = v;
        g_cur[i] = v;
    }
    if (i == 0) g_rowptr[n] = E;
}

__global__ void fill_kernel(const int* __restrict__ ei, int E, int n) {
    int e = blockIdx.x * blockDim.x + threadIdx.x;
    if (e < E) {
        int r = ei[e];
        int c = ei[E + e];
        if ((unsigned)r < (unsigned)n && (unsigned)c < (unsigned)n) {
            int pos = atomicAdd(&g_cur[c], 1);
            g_srcidx[pos] = r;
        }
    }
}

// ---------------------------------------------------------------------------
// fp16 tensor-core GEMM (m16n8k16), A-resident + cp.async double-buffered B,
// ldmatrix fragment loads.
//   As: [128][68] half2   34816 B ; Bs: [2][128][20] half2   20480 B
// ---------------------------------------------------------------------------
#define AS_LDH 68
#define BS_LDH 20
#define AS_BYTESH (128 * AS_LDH * 4)
#define BS_BYTESH (2 * 128 * BS_LDH * 4)
#define SMEM_TOTAL_GEMM (AS_BYTESH + BS_BYTESH)   // 55296

__device__ __forceinline__ void mma16(float* c, const uint32_t* a,
                                      uint32_t b0, uint32_t b1) {
    asm volatile(
        "mma.sync.aligned.m16n8k16.row.col.f32.f16.f16.f32 "
        "{%0,%1,%2,%3}, {%4,%5,%6,%7}, {%8,%9}, {%0,%1,%2,%3};"
        : "+f"(c[0]), "+f"(c[1]), "+f"(c[2]), "+f"(c[3])
        : "r"(a[0]), "r"(a[1]), "r"(a[2]), "r"(a[3]), "r"(b0), "r"(b1));
}

__device__ __forceinline__ void ldsm_x4(uint32_t& r0, uint32_t& r1,
                                        uint32_t& r2, uint32_t& r3,
                                        uint32_t saddr) {
    asm volatile("ldmatrix.sync.aligned.m8n8.x4.shared.b16 {%0,%1,%2,%3}, [%4];"
                 : "=r"(r0), "=r"(r1), "=r"(r2), "=r"(r3) : "r"(saddr));
}

__device__ __forceinline__ void cp_async16(void* sptr, const void* gptr) {
    uint32_t sa = (uint32_t)__cvta_generic_to_shared(sptr);
    asm volatile("cp.async.cg.shared.global [%0], [%1], 16;" :: "r"(sa), "l"(gptr));
}
__device__ __forceinline__ void cp_commit() {
    asm volatile("cp.async.commit_group;");
}
template <int NN>
__device__ __forceinline__ void cp_wait() {
    asm volatile("cp.async.wait_group %0;" :: "n"(NN));
}

__global__ __launch_bounds__(256) void fp16_gemm_kernel(
        const float* __restrict__ X, int M) {
    extern __shared__ char smem_raw[];
    uint32_t (*As)[AS_LDH]      = (uint32_t(*)[AS_LDH])smem_raw;
    uint32_t (*Bs)[128][BS_LDH] = (uint32_t(*)[128][BS_LDH])(smem_raw + AS_BYTESH);

    const int t    = threadIdx.x;
    const int wid  = t >> 5;
    const int lane = t & 31;
    const int warp_m = wid & 3;
    const int warp_n = wid >> 2;
    const int bm = blockIdx.x * 128;
    const int fr = lane >> 2;
    const int fc = lane & 3;

    const uint32_t as_base = (uint32_t)__cvta_generic_to_shared(&As[0][0]);
    const uint32_t bs_base = (uint32_t)__cvta_generic_to_shared(&Bs[0][0][0]);

    // ---- load full A tile (128 rows x 128 k) fp32 -> fp16 half2 ----
#pragma unroll
    for (int i = 0; i < 16; i++) {
        int idx = t + i * 256;
        int row = idx >> 5;
        int c4  = idx & 31;
        int gm  = bm + row;
        float4 v = make_float4(0.f, 0.f, 0.f, 0.f);
        if (gm < M) v = *(const float4*)&X[(size_t)gm * FF + c4 * 4];
        __half2 h0 = __floats2half2_rn(v.x, v.y);
        __half2 h1 = __floats2half2_rn(v.z, v.w);
        As[row][c4 * 2]     = *(uint32_t*)&h0;
        As[row][c4 * 2 + 1] = *(uint32_t*)&h1;
    }

    auto issueB = [&](int s, int buf) {
        int nt = s >> 2, kt = s & 3;
#pragma unroll
        for (int i = 0; i < 2; i++) {
            int idx = t + i * 256;
            int row = idx >> 2;
            int c16 = idx & 3;
            cp_async16(&Bs[buf][row][c16 * 4],
                       &g_wh[(size_t)(nt * 128 + row) * 64 + kt * 16 + c16 * 4]);
        }
        cp_commit();
    };

    issueB(0, 0);
    __syncthreads();

    float c[2][8][4];
#pragma unroll
    for (int mt = 0; mt < 2; mt++)
#pragma unroll
        for (int j = 0; j < 8; j++)
#pragma unroll
            for (int q = 0; q < 4; q++) c[mt][j][q] = 0.f;

    // ldmatrix lane address components (element units)
    const int a_row = warp_m * 32 + (lane & 15);      // + mt*16
    const int a_col = (lane >> 4) * 4;                // + kt*16 + ks*8 (half2)
    const int b_jj  = (lane >> 4);                    // j + 0/1
    const int b_row = warp_n * 64 + (lane & 7);       // + jj*8
    const int b_col = ((lane >> 3) & 1) * 4;          // + ks*8 (half2)

    for (int s = 0; s < 16; s++) {
        int buf = s & 1;
        if (s < 15) { issueB(s + 1, buf ^ 1); cp_wait<1>(); }
        else        { cp_wait<0>(); }
        __syncthreads();

        const int kt = s & 3;
#pragma unroll
        for (int ks = 0; ks < 2; ks++) {
            uint32_t a[2][4];
#pragma unroll
            for (int mt = 0; mt < 2; mt++) {
                uint32_t addr = as_base +
                    (uint32_t)(((a_row + mt * 16) * AS_LDH) + kt * 16 + ks * 8 + a_col) * 4;
                ldsm_x4(a[mt][0], a[mt][1], a[mt][2], a[mt][3], addr);
            }
#pragma unroll
            for (int j = 0; j < 8; j += 2) {
                uint32_t addr = bs_base + (uint32_t)buf * (128 * BS_LDH * 4) +
                    (uint32_t)(((b_row + (j + b_jj) * 8) * BS_LDH) + ks * 8 + b_col) * 4;
                uint32_t b0, b1, b2, b3;
                ldsm_x4(b0, b1, b2, b3, addr);
                mma16(c[0][j],     a[0], b0, b1);
                mma16(c[1][j],     a[1], b0, b1);
                mma16(c[0][j + 1], a[0], b2, b3);
                mma16(c[1][j + 1], a[1], b2, b3);
            }
        }
        __syncthreads();

        if ((s & 3) == 3) {
            int nt = s >> 2;
#pragma unroll
            for (int mt = 0; mt < 2; mt++) {
                int r0 = bm + warp_m * 32 + mt * 16 + fr;
                int r1 = r0 + 8;
                float s0 = (r0 < M) ? g_dinv[r0] : 0.f;
                float s1 = (r1 < M) ? g_dinv[r1] : 0.f;
#pragma unroll
                for (int j = 0; j < 8; j++) {
                    int colh = nt * 64 + warp_n * 32 + j * 4 + fc;
                    if (r0 < M) {
                        __half2 h = __floats2half2_rn(c[mt][j][0] * s0, c[mt][j][1] * s0);
                        g_h[(size_t)r0 * HH2 + colh] = *(uint32_t*)&h;
                    }
                    if (r1 < M) {
                        __half2 h = __floats2half2_rn(c[mt][j][2] * s1, c[mt][j][3] * s1);
                        g_h[(size_t)r1 * HH2 + colh] = *(uint32_t*)&h;
                    }
#pragma unroll
                    for (int q = 0; q < 4; q++) c[mt][j][q] = 0.f;
                }
            }
        }
    }
}

// ---------------------------------------------------------------------------
// Pull + finalize fused: one warp per node; fp16 gather (4-edge unroll),
// fp32 accumulate.
// ---------------------------------------------------------------------------
__device__ __forceinline__ void acc_uint4(float2* acc, uint4 v) {
    float2 f;
    f = __half22float2(*(__half2*)&v.x); acc[0].x += f.x; acc[0].y += f.y;
    f = __half22float2(*(__half2*)&v.y); acc[1].x += f.x; acc[1].y += f.y;
    f = __half22float2(*(__half2*)&v.z); acc[2].x += f.x; acc[2].y += f.y;
    f = __half22float2(*(__half2*)&v.w); acc[3].x += f.x; acc[3].y += f.y;
}

__global__ void pull_kernel(float* __restrict__ out,
                            const float* __restrict__ b,
                            const float* __restrict__ alpha,
                            int n) {
    int warp = (blockIdx.x * blockDim.x + threadIdx.x) >> 5;
    int lane = threadIdx.x & 31;
    if (warp >= n) return;
    int node = warp;
    int beg = g_rowptr[node];
    int end = g_rowptr[node + 1];

    const uint4* self = (const uint4*)&g_h[(size_t)node * HH2];
    float2 acc[2][4];
#pragma unroll
    for (int i = 0; i < 2; i++) {
        uint4 v = self[lane + i * 32];
        acc[i][0] = __half22float2(*(__half2*)&v.x);
        acc[i][1] = __half22float2(*(__half2*)&v.y);
        acc[i][2] = __half22float2(*(__half2*)&v.z);
        acc[i][3] = __half22float2(*(__half2*)&v.w);
    }

    int e = beg;
    for (; e + 3 < end; e += 4) {
        int r0 = g_srcidx[e];
        int r1 = g_srcidx[e + 1];
        int r2 = g_srcidx[e + 2];
        int r3 = g_srcidx[e + 3];
        const uint4* s0 = (const uint4*)&g_h[(size_t)r0 * HH2];
        const uint4* s1 = (const uint4*)&g_h[(size_t)r1 * HH2];
        const uint4* s2 = (const uint4*)&g_h[(size_t)r2 * HH2];
        const uint4* s3 = (const uint4*)&g_h[(size_t)r3 * HH2];
        uint4 v00 = s0[lane], v01 = s0[lane + 32];
        uint4 v10 = s1[lane], v11 = s1[lane + 32];
        uint4 v20 = s2[lane], v21 = s2[lane + 32];
        uint4 v30 = s3[lane], v31 = s3[lane + 32];
        acc_uint4(acc[0], v00); acc_uint4(acc[1], v01);
        acc_uint4(acc[0], v10); acc_uint4(acc[1], v11);
        acc_uint4(acc[0], v20); acc_uint4(acc[1], v21);
        acc_uint4(acc[0], v30); acc_uint4(acc[1], v31);
    }
    for (; e < end; e++) {
        int r0 = g_srcidx[e];
        const uint4* s0 = (const uint4*)&g_h[(size_t)r0 * HH2];
        acc_uint4(acc[0], s0[lane]);
        acc_uint4(acc[1], s0[lane + 32]);
    }

    float s = g_dinv[node];
    float* dst = &out[(size_t)node * HH];
#pragma unroll
    for (int i = 0; i < 2; i++) {
#pragma unroll
        for (int j = 0; j < 4; j++) {
            int colh = (lane + i * 32) * 4 + j;
            float2 bb = ((const float2*)b)[colh];
            float2 aa = ((const float2*)alpha)[colh];
            float2 v = acc[i][j];
            v.x = v.x * s + bb.x;  v.x = v.x > 0.f ? v.x : aa.x * v.x;
            v.y = v.y * s + bb.y;  v.y = v.y > 0.f ? v.y : aa.y * v.y;
            ((float2*)dst)[colh] = v;
        }
    }
}

// ---------------------------------------------------------------------------
// Launch
// ---------------------------------------------------------------------------
extern "C" void kernel_launch(void* const* d_in, const int* in_sizes, int n_in,
                              void* d_out, int out_size) {
    const float* x     = (const float*)d_in[0];  // [N, 128]
    const int*   ei    = (const int*)d_in[1];    // [2, E] int32
    const float* W     = (const float*)d_in[2];  // [512, 128]
    const float* b     = (const float*)d_in[3];  // [512]
    const float* alpha = (const float*)d_in[4];  // [512]
    float*       out   = (float*)d_out;          // [N, 512]

    const int N = in_sizes[0] / FF;
    const int E = in_sizes[1] / 2;
    const int nb = (N + SCAN_B - 1) / SCAN_B;
    const int countBlocks = (E + 255) / 256;
    const int wprepBlocks = (512 * 64 + 255) / 256;

    cudaFuncSetAttribute(fp16_gemm_kernel,
                         cudaFuncAttributeMaxDynamicSharedMemorySize,
                         SMEM_TOTAL_GEMM);

    // 1) count (by target) + W->fp16, fused
    count_wprep_kernel<<<countBlocks + wprepBlocks, 256>>>(ei, W, E, N, countBlocks);
    // 2) scan (+dinv, +re-zero), block offsets, CSR fill
    scan_block_kernel<<<nb, SCAN_B>>>(N);
    add_off_kernel<<<(N + 255) / 256, 256>>>(N, E, nb);
    fill_kernel<<<(E + 255) / 256, 256>>>(ei, E, N);

    // 3) g_h = fp16((x @ W^T) * dinv[row]) — fp16 TC + ldmatrix
    fp16_gemm_kernel<<<(N + 127) / 128, 256, SMEM_TOTAL_GEMM>>>(x, N);

    // 4) pull-based aggregate + finalize (warp per node)
    int warps_per_block = 256 / 32;
    pull_kernel<<<(N + warps_per_block - 1) / warps_per_block, 256>>>(out, b, alpha, N);
}

// round 12
// speedup vs baseline: 1.3951x; 1.0248x over previous
#include <cuda_runtime.h>
#include <cuda_fp16.h>
#include <cstdint>

#define FF 128
#define HH 512
#define HH2 256   // half2 per row
#define MAXN 50048
#define MAXE 401408
#define SCAN_B 1024

// Scratch (static device globals — no runtime allocation allowed)
__device__ __align__(16) uint32_t g_h[(size_t)50000 * HH2];  // h' rows fp16 (half2)
__device__ __align__(16) uint32_t g_wh[512 * 64];            // W fp16 (half2), [512][64]
__device__ int   g_cnt[MAXN];
__device__ float g_dinv[MAXN];
__device__ int   g_rowptr[MAXN + 1];
__device__ int   g_cur[MAXN];
__device__ int   g_srcidx[MAXE];
__device__ volatile int g_bval[64];
__device__ volatile int g_bflag[64];

// ---------------------------------------------------------------------------
// count (edge targets) + W->fp16 prep + lookback-flag reset, fused
// ---------------------------------------------------------------------------
__global__ void count_wprep_kernel(const int* __restrict__ ei,
                                   const float* __restrict__ W,
                                   int E, int n, int countBlocks) {
    int bid = blockIdx.x;
    if (bid == 0 && threadIdx.x < 64) {
        g_bflag[threadIdx.x] = 0;           // reset lookback flags for this run
        g_bval[threadIdx.x]  = 0;
    }
    if (bid < countBlocks) {
        int e = bid * 256 + threadIdx.x;
        if (e < E) {
            int c = ei[E + e];
            if ((unsigned)c < (unsigned)n) atomicAdd(&g_cnt[c], 1);
        }
    } else {
        int i = (bid - countBlocks) * 256 + threadIdx.x;   // half2 index
        if (i < 512 * 64) {
            float2 v = ((const float2*)W)[i];
            __half2 h = __floats2half2_rn(v.x, v.y);
            g_wh[i] = *(uint32_t*)&h;
        }
    }
}

// Fused scan: per-block scan + decoupled lookback + dinv + cnt re-zero +
// rowptr/cur writes. One kernel replaces scan_block + add_off.
__global__ void scan_fused_kernel(int n, int E) {
    __shared__ int sh[SCAN_B];
    __shared__ int exc;
    int bid = blockIdx.x;
    int gid = bid * SCAN_B + threadIdx.x;
    int v = 0;
    if (gid < n) {
        v = g_cnt[gid];
        g_cnt[gid] = 0;                       // restore zeros for replay determinism
        g_dinv[gid] = rsqrtf((float)(v + 1)); // +1 self-loop
    }
    sh[threadIdx.x] = v;
    __syncthreads();
#pragma unroll
    for (int off = 1; off < SCAN_B; off <<= 1) {
        int t = (threadIdx.x >= off) ? sh[threadIdx.x - off] : 0;
        __syncthreads();
        sh[threadIdx.x] += t;
        __syncthreads();
    }
    // publish block total, then look back over predecessors
    if (threadIdx.x == 0) {
        g_bval[bid] = sh[SCAN_B - 1];
        __threadfence();
        g_bflag[bid] = 1;
        int sum = 0;
        for (int j = bid - 1; j >= 0; j--) {
            while (g_bflag[j] == 0) { }
            sum += g_bval[j];
        }
        exc = sum;
    }
    __syncthreads();
    if (gid < n) {
        int val = sh[threadIdx.x] - v + exc;   // global exclusive prefix
        g_rowptr[gid] = val;
        g_cur[gid] = val;
    }
    if (gid == 0) g_rowptr[n] = E;
}

__global__ void fill_kernel(const int* __restrict__ ei, int E, int n) {
    int e = blockIdx.x * blockDim.x + threadIdx.x;
    if (e < E) {
        int r = ei[e];
        int c = ei[E + e];
        if ((unsigned)r < (unsigned)n && (unsigned)c < (unsigned)n) {
            int pos = atomicAdd(&g_cur[c], 1);
            g_srcidx[pos] = r;
        }
    }
}

// ---------------------------------------------------------------------------
// fp16 tensor-core GEMM (m16n8k16), A-resident + cp.async double-buffered B,
// ldmatrix fragment loads. (Round-11 known-good.)
// ---------------------------------------------------------------------------
#define AS_LDH 68
#define BS_LDH 20
#define AS_BYTESH (128 * AS_LDH * 4)
#define BS_BYTESH (2 * 128 * BS_LDH * 4)
#define SMEM_TOTAL_GEMM (AS_BYTESH + BS_BYTESH)   // 55296

__device__ __forceinline__ void mma16(float* c, const uint32_t* a,
                                      uint32_t b0, uint32_t b1) {
    asm volatile(
        "mma.sync.aligned.m16n8k16.row.col.f32.f16.f16.f32 "
        "{%0,%1,%2,%3}, {%4,%5,%6,%7}, {%8,%9}, {%0,%1,%2,%3};"
        : "+f"(c[0]), "+f"(c[1]), "+f"(c[2]), "+f"(c[3])
        : "r"(a[0]), "r"(a[1]), "r"(a[2]), "r"(a[3]), "r"(b0), "r"(b1));
}

__device__ __forceinline__ void ldsm_x4(uint32_t& r0, uint32_t& r1,
                                        uint32_t& r2, uint32_t& r3,
                                        uint32_t saddr) {
    asm volatile("ldmatrix.sync.aligned.m8n8.x4.shared.b16 {%0,%1,%2,%3}, [%4];"
                 : "=r"(r0), "=r"(r1), "=r"(r2), "=r"(r3) : "r"(saddr));
}

__device__ __forceinline__ void cp_async16(void* sptr, const void* gptr) {
    uint32_t sa = (uint32_t)__cvta_generic_to_shared(sptr);
    asm volatile("cp.async.cg.shared.global [%0], [%1], 16;" :: "r"(sa), "l"(gptr));
}
__device__ __forceinline__ void cp_commit() {
    asm volatile("cp.async.commit_group;");
}
template <int NN>
__device__ __forceinline__ void cp_wait() {
    asm volatile("cp.async.wait_group %0;" :: "n"(NN));
}

__global__ __launch_bounds__(256) void fp16_gemm_kernel(
        const float* __restrict__ X, int M) {
    extern __shared__ char smem_raw[];
    uint32_t (*As)[AS_LDH]      = (uint32_t(*)[AS_LDH])smem_raw;
    uint32_t (*Bs)[128][BS_LDH] = (uint32_t(*)[128][BS_LDH])(smem_raw + AS_BYTESH);

    const int t    = threadIdx.x;
    const int wid  = t >> 5;
    const int lane = t & 31;
    const int warp_m = wid & 3;
    const int warp_n = wid >> 2;
    const int bm = blockIdx.x * 128;
    const int fr = lane >> 2;
    const int fc = lane & 3;

    const uint32_t as_base = (uint32_t)__cvta_generic_to_shared(&As[0][0]);
    const uint32_t bs_base = (uint32_t)__cvta_generic_to_shared(&Bs[0][0][0]);

#pragma unroll
    for (int i = 0; i < 16; i++) {
        int idx = t + i * 256;
        int row = idx >> 5;
        int c4  = idx & 31;
        int gm  = bm + row;
        float4 v = make_float4(0.f, 0.f, 0.f, 0.f);
        if (gm < M) v = *(const float4*)&X[(size_t)gm * FF + c4 * 4];
        __half2 h0 = __floats2half2_rn(v.x, v.y);
        __half2 h1 = __floats2half2_rn(v.z, v.w);
        As[row][c4 * 2]     = *(uint32_t*)&h0;
        As[row][c4 * 2 + 1] = *(uint32_t*)&h1;
    }

    auto issueB = [&](int s, int buf) {
        int nt = s >> 2, kt = s & 3;
#pragma unroll
        for (int i = 0; i < 2; i++) {
            int idx = t + i * 256;
            int row = idx >> 2;
            int c16 = idx & 3;
            cp_async16(&Bs[buf][row][c16 * 4],
                       &g_wh[(size_t)(nt * 128 + row) * 64 + kt * 16 + c16 * 4]);
        }
        cp_commit();
    };

    issueB(0, 0);
    __syncthreads();

    float c[2][8][4];
#pragma unroll
    for (int mt = 0; mt < 2; mt++)
#pragma unroll
        for (int j = 0; j < 8; j++)
#pragma unroll
            for (int q = 0; q < 4; q++) c[mt][j][q] = 0.f;

    const int a_row = warp_m * 32 + (lane & 15);
    const int a_col = (lane >> 4) * 4;
    const int b_jj  = (lane >> 4);
    const int b_row = warp_n * 64 + (lane & 7);
    const int b_col = ((lane >> 3) & 1) * 4;

    for (int s = 0; s < 16; s++) {
        int buf = s & 1;
        if (s < 15) { issueB(s + 1, buf ^ 1); cp_wait<1>(); }
        else        { cp_wait<0>(); }
        __syncthreads();

        const int kt = s & 3;
#pragma unroll
        for (int ks = 0; ks < 2; ks++) {
            uint32_t a[2][4];
#pragma unroll
            for (int mt = 0; mt < 2; mt++) {
                uint32_t addr = as_base +
                    (uint32_t)(((a_row + mt * 16) * AS_LDH) + kt * 16 + ks * 8 + a_col) * 4;
                ldsm_x4(a[mt][0], a[mt][1], a[mt][2], a[mt][3], addr);
            }
#pragma unroll
            for (int j = 0; j < 8; j += 2) {
                uint32_t addr = bs_base + (uint32_t)buf * (128 * BS_LDH * 4) +
                    (uint32_t)(((b_row + (j + b_jj) * 8) * BS_LDH) + ks * 8 + b_col) * 4;
                uint32_t b0, b1, b2, b3;
                ldsm_x4(b0, b1, b2, b3, addr);
                mma16(c[0][j],     a[0], b0, b1);
                mma16(c[1][j],     a[1], b0, b1);
                mma16(c[0][j + 1], a[0], b2, b3);
                mma16(c[1][j + 1], a[1], b2, b3);
            }
        }
        __syncthreads();

        if ((s & 3) == 3) {
            int nt = s >> 2;
#pragma unroll
            for (int mt = 0; mt < 2; mt++) {
                int r0 = bm + warp_m * 32 + mt * 16 + fr;
                int r1 = r0 + 8;
                float s0 = (r0 < M) ? g_dinv[r0] : 0.f;
                float s1 = (r1 < M) ? g_dinv[r1] : 0.f;
#pragma unroll
                for (int j = 0; j < 8; j++) {
                    int colh = nt * 64 + warp_n * 32 + j * 4 + fc;
                    if (r0 < M) {
                        __half2 h = __floats2half2_rn(c[mt][j][0] * s0, c[mt][j][1] * s0);
                        g_h[(size_t)r0 * HH2 + colh] = *(uint32_t*)&h;
                    }
                    if (r1 < M) {
                        __half2 h = __floats2half2_rn(c[mt][j][2] * s1, c[mt][j][3] * s1);
                        g_h[(size_t)r1 * HH2 + colh] = *(uint32_t*)&h;
                    }
#pragma unroll
                    for (int q = 0; q < 4; q++) c[mt][j][q] = 0.f;
                }
            }
        }
    }
}

// ---------------------------------------------------------------------------
// Pull + finalize fused: one warp per node; fp16 gather (4-edge unroll),
// fp32 accumulate. Output via streaming stores (__stcs) to keep g_h L2-hot.
// ---------------------------------------------------------------------------
__device__ __forceinline__ void acc_uint4(float2* acc, uint4 v) {
    float2 f;
    f = __half22float2(*(__half2*)&v.x); acc[0].x += f.x; acc[0].y += f.y;
    f = __half22float2(*(__half2*)&v.y); acc[1].x += f.x; acc[1].y += f.y;
    f = __half22float2(*(__half2*)&v.z); acc[2].x += f.x; acc[2].y += f.y;
    f = __half22float2(*(__half2*)&v.w); acc[3].x += f.x; acc[3].y += f.y;
}

__global__ void pull_kernel(float* __restrict__ out,
                            const float* __restrict__ b,
                            const float* __restrict__ alpha,
                            int n) {
    int warp = (blockIdx.x * blockDim.x + threadIdx.x) >> 5;
    int lane = threadIdx.x & 31;
    if (warp >= n) return;
    int node = warp;
    int beg = g_rowptr[node];
    int end = g_rowptr[node + 1];

    const uint4* self = (const uint4*)&g_h[(size_t)node * HH2];
    float2 acc[2][4];
#pragma unroll
    for (int i = 0; i < 2; i++) {
        uint4 v = self[lane + i * 32];
        acc[i][0] = __half22float2(*(__half2*)&v.x);
        acc[i][1] = __half22float2(*(__half2*)&v.y);
        acc[i][2] = __half22float2(*(__half2*)&v.z);
        acc[i][3] = __half22float2(*(__half2*)&v.w);
    }

    int e = beg;
    for (; e + 3 < end; e += 4) {
        int r0 = g_srcidx[e];
        int r1 = g_srcidx[e + 1];
        int r2 = g_srcidx[e + 2];
        int r3 = g_srcidx[e + 3];
        const uint4* s0 = (const uint4*)&g_h[(size_t)r0 * HH2];
        const uint4* s1 = (const uint4*)&g_h[(size_t)r1 * HH2];
        const uint4* s2 = (const uint4*)&g_h[(size_t)r2 * HH2];
        const uint4* s3 = (const uint4*)&g_h[(size_t)r3 * HH2];
        uint4 v00 = s0[lane], v01 = s0[lane + 32];
        uint4 v10 = s1[lane], v11 = s1[lane + 32];
        uint4 v20 = s2[lane], v21 = s2[lane + 32];
        uint4 v30 = s3[lane], v31 = s3[lane + 32];
        acc_uint4(acc[0], v00); acc_uint4(acc[1], v01);
        acc_uint4(acc[0], v10); acc_uint4(acc[1], v11);
        acc_uint4(acc[0], v20); acc_uint4(acc[1], v21);
        acc_uint4(acc[0], v30); acc_uint4(acc[1], v31);
    }
    for (; e < end; e++) {
        int r0 = g_srcidx[e];
        const uint4* s0 = (const uint4*)&g_h[(size_t)r0 * HH2];
        acc_uint4(acc[0], s0[lane]);
        acc_uint4(acc[1], s0[lane + 32]);
    }

    float s = g_dinv[node];
    float* dst = &out[(size_t)node * HH];
#pragma unroll
    for (int i = 0; i < 2; i++) {
#pragma unroll
        for (int j = 0; j < 4; j += 2) {
            int colh = (lane + i * 32) * 4 + j;   // float2 index within row
            float4 bb = *(const float4*)&((const float2*)b)[colh];
            float4 aa = *(const float4*)&((const float2*)alpha)[colh];
            float2 v0 = acc[i][j];
            float2 v1 = acc[i][j + 1];
            float4 r;
            r.x = v0.x * s + bb.x;  r.x = r.x > 0.f ? r.x : aa.x * r.x;
            r.y = v0.y * s + bb.y;  r.y = r.y > 0.f ? r.y : aa.y * r.y;
            r.z = v1.x * s + bb.z;  r.z = r.z > 0.f ? r.z : aa.z * r.z;
            r.w = v1.y * s + bb.w;  r.w = r.w > 0.f ? r.w : aa.w * r.w;
            __stcs((float4*)&((float2*)dst)[colh], r);   // streaming: evict-first
        }
    }
}

// ---------------------------------------------------------------------------
// Launch
// ---------------------------------------------------------------------------
extern "C" void kernel_launch(void* const* d_in, const int* in_sizes, int n_in,
                              void* d_out, int out_size) {
    const float* x     = (const float*)d_in[0];  // [N, 128]
    const int*   ei    = (const int*)d_in[1];    // [2, E] int32
    const float* W     = (const float*)d_in[2];  // [512, 128]
    const float* b     = (const float*)d_in[3];  // [512]
    const float* alpha = (const float*)d_in[4];  // [512]
    float*       out   = (float*)d_out;          // [N, 512]

    const int N = in_sizes[0] / FF;
    const int E = in_sizes[1] / 2;
    const int nb = (N + SCAN_B - 1) / SCAN_B;
    const int countBlocks = (E + 255) / 256;
    const int wprepBlocks = (512 * 64 + 255) / 256;

    cudaFuncSetAttribute(fp16_gemm_kernel,
                         cudaFuncAttributeMaxDynamicSharedMemorySize,
                         SMEM_TOTAL_GEMM);

    // 1) count (by target) + W->fp16 + lookback-flag reset, fused
    count_wprep_kernel<<<countBlocks + wprepBlocks, 256>>>(ei, W, E, N, countBlocks);
    // 2) fused scan (dinv, cnt re-zero, rowptr, cur) — decoupled lookback
    scan_fused_kernel<<<nb, SCAN_B>>>(N, E);
    // 3) CSR fill
    fill_kernel<<<(E + 255) / 256, 256>>>(ei, E, N);

    // 4) g_h = fp16((x @ W^T) * dinv[row]) — fp16 TC + ldmatrix
    fp16_gemm_kernel<<<(N + 127) / 128, 256, SMEM_TOTAL_GEMM>>>(x, N);

    // 5) pull-based aggregate + finalize (warp per node, streaming out stores)
    int warps_per_block = 256 / 32;
    pull_kernel<<<(N + warps_per_block - 1) / warps_per_block, 256>>>(out, b, alpha, N);
}